// round 12
// baseline (speedup 1.0000x reference)
#include <cuda_runtime.h>
#include <cuda_fp16.h>

#define F_IN  14
#define HEADS 8
#define DIM   8
#define F1    64          // HEADS*DIM
#define NEG   0.2f
#define MAXN  100000
#define MAXE  1600000
#define TILE  1024
#define MAXT  ((MAXN + TILE - 1) / TILE)

// ------------------------- scratch (device globals; no allocs) -------------
__device__ __half g_h1h[MAXN * F1];     // layer1 linear output, fp16 [N,64]
__device__ float g_hL2 [MAXN * F1];     // layer1 final output (ELU'd) = layer2 input
__device__ float g_as1 [MAXN * HEADS];
__device__ float g_ad1 [MAXN * HEADS];
__device__ float g_h2  [MAXN * DIM];    // layer2 linear output [N,8]
__device__ float g_as2 [MAXN];
__device__ float g_ad2 [MAXN];
__device__ int   g_ssrc[MAXE];          // src ids sorted by dst (CSR col idx)
__device__ int   g_cnt [MAXN];          // in-degree histogram
__device__ int   g_off [MAXN + 1];      // CSR row offsets
__device__ int   g_cur [MAXN];          // scatter cursors
__device__ int   g_look[MAXT];          // lookback: -1 = pending, else inclusive prefix
__device__ int   g_is64;

// ------------------------- helpers ----------------------------------------
__device__ __forceinline__ float lrelu(float x) { return x > 0.f ? x : NEG * x; }

__device__ __forceinline__ void acc8h(const uint4 u, float w, float4& a0, float4& a1) {
    float2 p0 = __half22float2(*(const __half2*)&u.x);
    float2 p1 = __half22float2(*(const __half2*)&u.y);
    float2 p2 = __half22float2(*(const __half2*)&u.z);
    float2 p3 = __half22float2(*(const __half2*)&u.w);
    a0.x += p0.x * w; a0.y += p0.y * w; a0.z += p1.x * w; a0.w += p1.y * w;
    a1.x += p2.x * w; a1.y += p2.y * w; a1.z += p3.x * w; a1.w += p3.y * w;
}

// ------------------------- CSR build ---------------------------------------
// zero histogram + init lookback sentinels + (block 0) dtype detect
__global__ void k_zero(const unsigned long long* p, int n, int ntiles) {
    int i = blockIdx.x * blockDim.x + threadIdx.x;
    if (i < n) g_cnt[i] = 0;
    if (i < ntiles) g_look[i] = -1;
    if (blockIdx.x == 0 && threadIdx.x == 0) {
        int is64 = 1;
        for (int k = 0; k < 64; k++)
            if (p[k] >> 32) { is64 = 0; break; }
        g_is64 = is64;
    }
}

__global__ void k_hist(const void* ei, int e) {
    int i = blockIdx.x * blockDim.x + threadIdx.x;
    if (i >= e) return;
    int d = g_is64 ? (int)((const long long*)ei)[e + i]
                   : ((const int*)ei)[e + i];
    atomicAdd(&g_cnt[d], 1);
}

// single-pass exclusive scan: per-tile block scan + chained decoupled lookback.
// 98 blocks, all resident in wave 1 -> predecessor always makes progress.
__global__ void __launch_bounds__(256) k_scan1(int n, int e) {
    __shared__ int sp[256];
    __shared__ int sprefix;
    int base = blockIdx.x * TILE;
    int t = threadIdx.x;
    int v[4]; int s = 0;
#pragma unroll
    for (int k = 0; k < 4; k++) {
        int i = base + t * 4 + k;
        v[k] = (i < n) ? g_cnt[i] : 0;
        s += v[k];
    }
    sp[t] = s;
    __syncthreads();
#pragma unroll
    for (int off = 1; off < 256; off <<= 1) {
        int u = (t >= off) ? sp[t - off] : 0;
        __syncthreads();
        sp[t] += u;
        __syncthreads();
    }
    if (t == 0) {
        int pre = 0;
        if (blockIdx.x > 0)
            do { pre = atomicAdd(&g_look[blockIdx.x - 1], 0); } while (pre < 0);
        atomicExch(&g_look[blockIdx.x], pre + sp[255]);   // publish inclusive prefix
        sprefix = pre;
    }
    __syncthreads();
    int run = sprefix + sp[t] - s;        // exclusive within block + chain prefix
#pragma unroll
    for (int k = 0; k < 4; k++) {
        int i = base + t * 4 + k;
        if (i < n) { g_off[i] = run; g_cur[i] = run; run += v[k]; }
    }
    if (blockIdx.x == gridDim.x - 1 && t == 0) g_off[n] = e;
}

__global__ void k_scatter(const void* ei, int e) {
    int i = blockIdx.x * blockDim.x + threadIdx.x;
    if (i >= e) return;
    int s, d;
    if (g_is64) {
        const long long* p = (const long long*)ei;
        s = (int)p[i]; d = (int)p[e + i];
    } else {
        const int* p = (const int*)ei;
        s = p[i]; d = p[e + i];
    }
    int pos = atomicAdd(&g_cur[d], 1);
    g_ssrc[pos] = s;
}

// ------------------------- layer 1: fused gemm + logits --------------------
__global__ void __launch_bounds__(256) k_l1(const float* __restrict__ x,
                                            const float* __restrict__ W1,
                                            const float* __restrict__ asrc,
                                            const float* __restrict__ adst, int n) {
    __shared__ float sW[F_IN * F1];
    __shared__ float sS[F1], sD[F1];
    int tid = threadIdx.x;
    for (int i = tid; i < F_IN * F1; i += 256) sW[i] = W1[i];
    if (tid < F1) { sS[tid] = asrc[tid]; sD[tid] = adst[tid]; }
    __syncthreads();

    int node = blockIdx.x * 4 + (tid >> 6);
    int c = tid & 63;
    if (node >= n) return;

    const float* xr = x + node * F_IN;
    float acc = 0.f;
#pragma unroll
    for (int k = 0; k < F_IN; k++) acc += xr[k] * sW[k * F1 + c];
    g_h1h[node * F1 + c] = __float2half_rn(acc);

    float as = acc * sS[c], ad = acc * sD[c];
#pragma unroll
    for (int m = 1; m < 8; m <<= 1) {
        as += __shfl_xor_sync(0xffffffffu, as, m, 8);
        ad += __shfl_xor_sync(0xffffffffu, ad, m, 8);
    }
    if ((c & 7) == 0) {
        int j = node * HEADS + (c >> 3);
        g_as1[j] = as;
        g_ad1[j] = ad;
    }
}

// ------------------------- layer 1: dst-centric gather + normalize+ELU -----
// 8 threads per node; fp16 feature rows (one uint4 per edge); 2-edge pipeline.
__global__ void __launch_bounds__(256) k_gather1(const float* __restrict__ b1, int n) {
    int tid = threadIdx.x;
    int node = blockIdx.x * 32 + (tid >> 3);
    int h = tid & 7;
    if (node >= n) return;

    int beg = g_off[node], end = g_off[node + 1];
    float ad = g_ad1[node * 8 + h];

    float4 acc0 = make_float4(0.f, 0.f, 0.f, 0.f);
    float4 acc1 = make_float4(0.f, 0.f, 0.f, 0.f);

    float wl = __expf(lrelu(g_as1[node * 8 + h] + ad));
    acc8h(*(const uint4*)(g_h1h + node * F1 + h * 8), wl, acc0, acc1);
    float ws = wl;

    int j = beg;
    for (; j + 1 < end; j += 2) {
        int s0 = g_ssrc[j], s1 = g_ssrc[j + 1];
        float e0 = g_as1[s0 * 8 + h], e1 = g_as1[s1 * 8 + h];
        uint4 u = *(const uint4*)(g_h1h + s0 * F1 + h * 8);
        uint4 v = *(const uint4*)(g_h1h + s1 * F1 + h * 8);
        float w0 = __expf(lrelu(e0 + ad));
        float w1 = __expf(lrelu(e1 + ad));
        acc8h(u, w0, acc0, acc1);
        acc8h(v, w1, acc0, acc1);
        ws += w0 + w1;
    }
    if (j < end) {
        int s = g_ssrc[j];
        float w = __expf(lrelu(g_as1[s * 8 + h] + ad));
        acc8h(*(const uint4*)(g_h1h + s * F1 + h * 8), w, acc0, acc1);
        ws += w;
    }

    float r = __fdividef(1.f, ws);
    float4 bb0 = *(const float4*)(b1 + h * 8);
    float4 bb1 = *(const float4*)(b1 + h * 8 + 4);
    float4 o0, o1;
    o0.x = acc0.x * r + bb0.x; o0.x = o0.x > 0.f ? o0.x : expm1f(o0.x);
    o0.y = acc0.y * r + bb0.y; o0.y = o0.y > 0.f ? o0.y : expm1f(o0.y);
    o0.z = acc0.z * r + bb0.z; o0.z = o0.z > 0.f ? o0.z : expm1f(o0.z);
    o0.w = acc0.w * r + bb0.w; o0.w = o0.w > 0.f ? o0.w : expm1f(o0.w);
    o1.x = acc1.x * r + bb1.x; o1.x = o1.x > 0.f ? o1.x : expm1f(o1.x);
    o1.y = acc1.y * r + bb1.y; o1.y = o1.y > 0.f ? o1.y : expm1f(o1.y);
    o1.z = acc1.z * r + bb1.z; o1.z = o1.z > 0.f ? o1.z : expm1f(o1.z);
    o1.w = acc1.w * r + bb1.w; o1.w = o1.w > 0.f ? o1.w : expm1f(o1.w);
    *(float4*)(g_hL2 + node * F1 + h * 8)     = o0;
    *(float4*)(g_hL2 + node * F1 + h * 8 + 4) = o1;
}

// ------------------------- layer 2: gemm + logits ---------------------------
__global__ void __launch_bounds__(256) k_l2(const float* __restrict__ W2,
                                            const float* __restrict__ asrc,
                                            const float* __restrict__ adst, int n) {
    __shared__ float sW[F1 * DIM], sS[DIM], sD[DIM];
    int tid = threadIdx.x;
    for (int i = tid; i < F1 * DIM; i += 256) sW[i] = W2[i];
    if (tid < DIM) { sS[tid] = asrc[tid]; sD[tid] = adst[tid]; }
    __syncthreads();

    int nidx = blockIdx.x * blockDim.x + tid;
    if (nidx >= n) return;

    float acc[DIM] = {0.f,0.f,0.f,0.f,0.f,0.f,0.f,0.f};
    const float* row = g_hL2 + nidx * F1;
#pragma unroll
    for (int k = 0; k < F1; k += 4) {
        float4 t = *(const float4*)(row + k);
#pragma unroll
        for (int c = 0; c < DIM; c++)
            acc[c] += t.x * sW[k * 8 + c] + t.y * sW[(k + 1) * 8 + c]
                    + t.z * sW[(k + 2) * 8 + c] + t.w * sW[(k + 3) * 8 + c];
    }
    float as = 0.f, ad = 0.f;
#pragma unroll
    for (int c = 0; c < DIM; c++) {
        as += acc[c] * sS[c];
        ad += acc[c] * sD[c];
        g_h2[nidx * DIM + c] = acc[c];
    }
    g_as2[nidx] = as;
    g_ad2[nidx] = ad;
}

// ------------------------- layer 2: dst-centric gather + finalize ----------
__global__ void __launch_bounds__(256) k_gather2(const float* __restrict__ b2,
                                                 int n, float* __restrict__ out) {
    int tid = threadIdx.x;
    int node = blockIdx.x * 32 + (tid >> 3);
    int c = tid & 7;
    if (node >= n) return;

    int beg = g_off[node], end = g_off[node + 1];
    float ad = g_ad2[node];

    float wl = __expf(lrelu(g_as2[node] + ad));
    float acc = g_h2[node * DIM + c] * wl;
    float ws = wl;

    int j = beg;
    for (; j + 3 < end; j += 4) {
        int s0 = g_ssrc[j],     s1 = g_ssrc[j + 1];
        int s2 = g_ssrc[j + 2], s3 = g_ssrc[j + 3];
        float e0 = g_as2[s0], e1 = g_as2[s1], e2 = g_as2[s2], e3 = g_as2[s3];
        float f0 = g_h2[s0 * DIM + c], f1 = g_h2[s1 * DIM + c];
        float f2 = g_h2[s2 * DIM + c], f3 = g_h2[s3 * DIM + c];
        float w0 = __expf(lrelu(e0 + ad)), w1 = __expf(lrelu(e1 + ad));
        float w2 = __expf(lrelu(e2 + ad)), w3 = __expf(lrelu(e3 + ad));
        acc += w0 * f0 + w1 * f1 + w2 * f2 + w3 * f3;
        ws  += w0 + w1 + w2 + w3;
    }
    for (; j < end; j++) {
        int s = g_ssrc[j];
        float w = __expf(lrelu(g_as2[s] + ad));
        acc += w * g_h2[s * DIM + c];
        ws += w;
    }
    out[node * DIM + c] = acc * __fdividef(1.f, ws) + __ldg(&b2[c]);
}

// ------------------------- launch -----------------------------------------
extern "C" void kernel_launch(void* const* d_in, const int* in_sizes, int n_in,
                              void* d_out, int out_size) {
    const float* x   = (const float*)d_in[0];
    const void*  ei  = d_in[1];
    const float* W1  = (const float*)d_in[2];
    const float* as1 = (const float*)d_in[3];
    const float* ad1 = (const float*)d_in[4];
    const float* b1  = (const float*)d_in[5];
    const float* W2  = (const float*)d_in[6];
    const float* as2 = (const float*)d_in[7];
    const float* ad2 = (const float*)d_in[8];
    const float* b2  = (const float*)d_in[9];
    float* out = (float*)d_out;

    int n = in_sizes[0] / F_IN;
    int e = in_sizes[1] / 2;
    const int B = 256;
    auto g = [&](long long t) { return (unsigned)((t + B - 1) / B); };
    int ntiles = (n + TILE - 1) / TILE;

    // CSR build (7 launches total now)
    k_zero    <<<g(n), B>>>((const unsigned long long*)ei, n, ntiles);
    k_hist    <<<g(e), B>>>(ei, e);
    k_scan1   <<<ntiles, B>>>(n, e);
    k_scatter <<<g(e), B>>>(ei, e);

    // layer 1
    k_l1      <<<(n + 3) / 4, B>>>(x, W1, as1, ad1, n);
    k_gather1 <<<(n + 31) / 32, B>>>(b1, n);

    // layer 2
    k_l2      <<<g(n), B>>>(W2, as2, ad2, n);
    k_gather2 <<<(n + 31) / 32, B>>>(b2, n, out);
}

// round 13
// speedup vs baseline: 1.2406x; 1.2406x over previous
#include <cuda_runtime.h>
#include <cuda_fp16.h>

#define F_IN  14
#define HEADS 8
#define DIM   8
#define F1    64          // HEADS*DIM
#define NEG   0.2f
#define MAXN  100000
#define MAXE  1600000
#define TILE  1024
#define MAXT  ((MAXN + TILE - 1) / TILE)

// ------------------------- scratch (device globals; no allocs) -------------
__device__ __half g_h1h[MAXN * F1];     // layer1 linear output, fp16 [N,64]
__device__ float g_hL2 [MAXN * F1];     // layer1 final output (ELU'd) = layer2 input
__device__ float g_as1 [MAXN * HEADS];
__device__ float g_ad1 [MAXN * HEADS];
__device__ float g_h2  [MAXN * DIM];    // layer2 linear output [N,8]
__device__ float g_as2 [MAXN];
__device__ float g_ad2 [MAXN];
__device__ int   g_ssrc[MAXE];          // src ids sorted by dst (CSR col idx)
__device__ int   g_rank[MAXE];          // per-edge rank within its dst bucket
__device__ int   g_cnt [MAXN];          // in-degree histogram
__device__ int   g_off [MAXN + 1];      // CSR row offsets
__device__ int   g_bsum[MAXT];          // per-tile sums
__device__ int   g_bpre[MAXT];          // per-tile exclusive prefixes
__device__ int   g_is64;

// ------------------------- helpers ----------------------------------------
__device__ __forceinline__ float lrelu(float x) { return x > 0.f ? x : NEG * x; }

__device__ __forceinline__ void acc8h(const uint4 u, float w, float4& a0, float4& a1) {
    float2 p0 = __half22float2(*(const __half2*)&u.x);
    float2 p1 = __half22float2(*(const __half2*)&u.y);
    float2 p2 = __half22float2(*(const __half2*)&u.z);
    float2 p3 = __half22float2(*(const __half2*)&u.w);
    a0.x += p0.x * w; a0.y += p0.y * w; a0.z += p1.x * w; a0.w += p1.y * w;
    a1.x += p2.x * w; a1.y += p2.y * w; a1.z += p3.x * w; a1.w += p3.y * w;
}

// ------------------------- CSR build ---------------------------------------
// zero histogram + (block 0) edge dtype detect
__global__ void k_zero(const unsigned long long* p, int n) {
    int i = blockIdx.x * blockDim.x + threadIdx.x;
    if (i < n) g_cnt[i] = 0;
    if (blockIdx.x == 0 && threadIdx.x == 0) {
        int is64 = 1;
        for (int k = 0; k < 64; k++)
            if (p[k] >> 32) { is64 = 0; break; }
        g_is64 = is64;
    }
}

// dst histogram + record each edge's rank within its dst bucket
__global__ void k_hist(const void* ei, int e) {
    int i = blockIdx.x * blockDim.x + threadIdx.x;
    if (i >= e) return;
    int d = g_is64 ? (int)((const long long*)ei)[e + i]
                   : ((const int*)ei)[e + i];
    g_rank[i] = atomicAdd(&g_cnt[d], 1);
}

// ---- hierarchical scan: tile sums -> tiny scan -> per-tile offsets --------
__global__ void __launch_bounds__(256) k_tilesum(int n) {
    __shared__ int sw[8];
    int base = blockIdx.x * TILE;
    int t = threadIdx.x;
    int s = 0;
#pragma unroll
    for (int k = 0; k < 4; k++) {
        int i = base + t * 4 + k;
        if (i < n) s += g_cnt[i];
    }
#pragma unroll
    for (int m = 16; m; m >>= 1) s += __shfl_xor_sync(0xffffffffu, s, m);
    if ((t & 31) == 0) sw[t >> 5] = s;
    __syncthreads();
    if (t == 0) {
        int tot = 0;
#pragma unroll
        for (int w = 0; w < 8; w++) tot += sw[w];
        g_bsum[blockIdx.x] = tot;
    }
}

__global__ void __launch_bounds__(128) k_scanb(int ntiles, int n, int e) {
    __shared__ int sp[128];
    int t = threadIdx.x;
    int v = (t < ntiles) ? g_bsum[t] : 0;
    sp[t] = v;
    __syncthreads();
#pragma unroll
    for (int off = 1; off < 128; off <<= 1) {
        int u = (t >= off) ? sp[t - off] : 0;
        __syncthreads();
        sp[t] += u;
        __syncthreads();
    }
    if (t < ntiles) g_bpre[t] = sp[t] - v;
    if (t == 0) g_off[n] = e;
}

__global__ void __launch_bounds__(256) k_offsets(int n) {
    __shared__ int sp[256];
    int base = blockIdx.x * TILE;
    int t = threadIdx.x;
    int v[4]; int s = 0;
#pragma unroll
    for (int k = 0; k < 4; k++) {
        int i = base + t * 4 + k;
        v[k] = (i < n) ? g_cnt[i] : 0;
        s += v[k];
    }
    sp[t] = s;
    __syncthreads();
#pragma unroll
    for (int off = 1; off < 256; off <<= 1) {
        int u = (t >= off) ? sp[t - off] : 0;
        __syncthreads();
        sp[t] += u;
        __syncthreads();
    }
    int run = g_bpre[blockIdx.x] + sp[t] - s;
#pragma unroll
    for (int k = 0; k < 4; k++) {
        int i = base + t * 4 + k;
        if (i < n) { g_off[i] = run; run += v[k]; }
    }
}

// scatter with precomputed ranks: pos = off[d] + rank[i], no atomics
__global__ void k_scatter(const void* ei, int e) {
    int i = blockIdx.x * blockDim.x + threadIdx.x;
    if (i >= e) return;
    int s, d;
    if (g_is64) {
        const long long* p = (const long long*)ei;
        s = (int)p[i]; d = (int)p[e + i];
    } else {
        const int* p = (const int*)ei;
        s = p[i]; d = p[e + i];
    }
    g_ssrc[g_off[d] + g_rank[i]] = s;
}

// ------------------------- layer 1: fused gemm + logits --------------------
__global__ void __launch_bounds__(256) k_l1(const float* __restrict__ x,
                                            const float* __restrict__ W1,
                                            const float* __restrict__ asrc,
                                            const float* __restrict__ adst, int n) {
    __shared__ float sW[F_IN * F1];
    __shared__ float sS[F1], sD[F1];
    int tid = threadIdx.x;
    for (int i = tid; i < F_IN * F1; i += 256) sW[i] = W1[i];
    if (tid < F1) { sS[tid] = asrc[tid]; sD[tid] = adst[tid]; }
    __syncthreads();

    int node = blockIdx.x * 4 + (tid >> 6);
    int c = tid & 63;
    if (node >= n) return;

    const float* xr = x + node * F_IN;
    float acc = 0.f;
#pragma unroll
    for (int k = 0; k < F_IN; k++) acc += xr[k] * sW[k * F1 + c];
    g_h1h[node * F1 + c] = __float2half_rn(acc);

    float as = acc * sS[c], ad = acc * sD[c];
#pragma unroll
    for (int m = 1; m < 8; m <<= 1) {
        as += __shfl_xor_sync(0xffffffffu, as, m, 8);
        ad += __shfl_xor_sync(0xffffffffu, ad, m, 8);
    }
    if ((c & 7) == 0) {
        int j = node * HEADS + (c >> 3);
        g_as1[j] = as;
        g_ad1[j] = ad;
    }
}

// ------------------------- layer 1: dst-centric gather + normalize+ELU -----
// 8 threads per node; fp16 feature rows (one uint4 per edge); 2-edge pipeline.
__global__ void __launch_bounds__(256) k_gather1(const float* __restrict__ b1, int n) {
    int tid = threadIdx.x;
    int node = blockIdx.x * 32 + (tid >> 3);
    int h = tid & 7;
    if (node >= n) return;

    int beg = g_off[node], end = g_off[node + 1];
    float ad = g_ad1[node * 8 + h];

    float4 acc0 = make_float4(0.f, 0.f, 0.f, 0.f);
    float4 acc1 = make_float4(0.f, 0.f, 0.f, 0.f);

    float wl = __expf(lrelu(g_as1[node * 8 + h] + ad));
    acc8h(*(const uint4*)(g_h1h + node * F1 + h * 8), wl, acc0, acc1);
    float ws = wl;

    int j = beg;
    for (; j + 1 < end; j += 2) {
        int s0 = g_ssrc[j], s1 = g_ssrc[j + 1];
        float e0 = g_as1[s0 * 8 + h], e1 = g_as1[s1 * 8 + h];
        uint4 u = *(const uint4*)(g_h1h + s0 * F1 + h * 8);
        uint4 v = *(const uint4*)(g_h1h + s1 * F1 + h * 8);
        float w0 = __expf(lrelu(e0 + ad));
        float w1 = __expf(lrelu(e1 + ad));
        acc8h(u, w0, acc0, acc1);
        acc8h(v, w1, acc0, acc1);
        ws += w0 + w1;
    }
    if (j < end) {
        int s = g_ssrc[j];
        float w = __expf(lrelu(g_as1[s * 8 + h] + ad));
        acc8h(*(const uint4*)(g_h1h + s * F1 + h * 8), w, acc0, acc1);
        ws += w;
    }

    float r = __fdividef(1.f, ws);
    float4 bb0 = *(const float4*)(b1 + h * 8);
    float4 bb1 = *(const float4*)(b1 + h * 8 + 4);
    float4 o0, o1;
    o0.x = acc0.x * r + bb0.x; o0.x = o0.x > 0.f ? o0.x : expm1f(o0.x);
    o0.y = acc0.y * r + bb0.y; o0.y = o0.y > 0.f ? o0.y : expm1f(o0.y);
    o0.z = acc0.z * r + bb0.z; o0.z = o0.z > 0.f ? o0.z : expm1f(o0.z);
    o0.w = acc0.w * r + bb0.w; o0.w = o0.w > 0.f ? o0.w : expm1f(o0.w);
    o1.x = acc1.x * r + bb1.x; o1.x = o1.x > 0.f ? o1.x : expm1f(o1.x);
    o1.y = acc1.y * r + bb1.y; o1.y = o1.y > 0.f ? o1.y : expm1f(o1.y);
    o1.z = acc1.z * r + bb1.z; o1.z = o1.z > 0.f ? o1.z : expm1f(o1.z);
    o1.w = acc1.w * r + bb1.w; o1.w = o1.w > 0.f ? o1.w : expm1f(o1.w);
    *(float4*)(g_hL2 + node * F1 + h * 8)     = o0;
    *(float4*)(g_hL2 + node * F1 + h * 8 + 4) = o1;
}

// ------------------------- layer 2: gemm + logits ---------------------------
__global__ void __launch_bounds__(256) k_l2(const float* __restrict__ W2,
                                            const float* __restrict__ asrc,
                                            const float* __restrict__ adst, int n) {
    __shared__ float sW[F1 * DIM], sS[DIM], sD[DIM];
    int tid = threadIdx.x;
    for (int i = tid; i < F1 * DIM; i += 256) sW[i] = W2[i];
    if (tid < DIM) { sS[tid] = asrc[tid]; sD[tid] = adst[tid]; }
    __syncthreads();

    int nidx = blockIdx.x * blockDim.x + tid;
    if (nidx >= n) return;

    float acc[DIM] = {0.f,0.f,0.f,0.f,0.f,0.f,0.f,0.f};
    const float* row = g_hL2 + nidx * F1;
#pragma unroll
    for (int k = 0; k < F1; k += 4) {
        float4 t = *(const float4*)(row + k);
#pragma unroll
        for (int c = 0; c < DIM; c++)
            acc[c] += t.x * sW[k * 8 + c] + t.y * sW[(k + 1) * 8 + c]
                    + t.z * sW[(k + 2) * 8 + c] + t.w * sW[(k + 3) * 8 + c];
    }
    float as = 0.f, ad = 0.f;
#pragma unroll
    for (int c = 0; c < DIM; c++) {
        as += acc[c] * sS[c];
        ad += acc[c] * sD[c];
        g_h2[nidx * DIM + c] = acc[c];
    }
    g_as2[nidx] = as;
    g_ad2[nidx] = ad;
}

// ------------------------- layer 2: dst-centric gather + finalize ----------
__global__ void __launch_bounds__(256) k_gather2(const float* __restrict__ b2,
                                                 int n, float* __restrict__ out) {
    int tid = threadIdx.x;
    int node = blockIdx.x * 32 + (tid >> 3);
    int c = tid & 7;
    if (node >= n) return;

    int beg = g_off[node], end = g_off[node + 1];
    float ad = g_ad2[node];

    float wl = __expf(lrelu(g_as2[node] + ad));
    float acc = g_h2[node * DIM + c] * wl;
    float ws = wl;

    int j = beg;
    for (; j + 3 < end; j += 4) {
        int s0 = g_ssrc[j],     s1 = g_ssrc[j + 1];
        int s2 = g_ssrc[j + 2], s3 = g_ssrc[j + 3];
        float e0 = g_as2[s0], e1 = g_as2[s1], e2 = g_as2[s2], e3 = g_as2[s3];
        float f0 = g_h2[s0 * DIM + c], f1 = g_h2[s1 * DIM + c];
        float f2 = g_h2[s2 * DIM + c], f3 = g_h2[s3 * DIM + c];
        float w0 = __expf(lrelu(e0 + ad)), w1 = __expf(lrelu(e1 + ad));
        float w2 = __expf(lrelu(e2 + ad)), w3 = __expf(lrelu(e3 + ad));
        acc += w0 * f0 + w1 * f1 + w2 * f2 + w3 * f3;
        ws  += w0 + w1 + w2 + w3;
    }
    for (; j < end; j++) {
        int s = g_ssrc[j];
        float w = __expf(lrelu(g_as2[s] + ad));
        acc += w * g_h2[s * DIM + c];
        ws += w;
    }
    out[node * DIM + c] = acc * __fdividef(1.f, ws) + __ldg(&b2[c]);
}

// ------------------------- launch -----------------------------------------
extern "C" void kernel_launch(void* const* d_in, const int* in_sizes, int n_in,
                              void* d_out, int out_size) {
    const float* x   = (const float*)d_in[0];
    const void*  ei  = d_in[1];
    const float* W1  = (const float*)d_in[2];
    const float* as1 = (const float*)d_in[3];
    const float* ad1 = (const float*)d_in[4];
    const float* b1  = (const float*)d_in[5];
    const float* W2  = (const float*)d_in[6];
    const float* as2 = (const float*)d_in[7];
    const float* ad2 = (const float*)d_in[8];
    const float* b2  = (const float*)d_in[9];
    float* out = (float*)d_out;

    int n = in_sizes[0] / F_IN;
    int e = in_sizes[1] / 2;
    const int B = 256;
    auto g = [&](long long t) { return (unsigned)((t + B - 1) / B); };
    int ntiles = (n + TILE - 1) / TILE;

    // CSR build (rank-precomputed scatter: no atomics in k_scatter)
    k_zero    <<<g(n), B>>>((const unsigned long long*)ei, n);
    k_hist    <<<g(e), B>>>(ei, e);
    k_tilesum <<<ntiles, B>>>(n);
    k_scanb   <<<1, 128>>>(ntiles, n, e);
    k_offsets <<<ntiles, B>>>(n);
    k_scatter <<<g(e), B>>>(ei, e);

    // layer 1
    k_l1      <<<(n + 3) / 4, B>>>(x, W1, as1, ad1, n);
    k_gather1 <<<(n + 31) / 32, B>>>(b1, n);

    // layer 2
    k_l2      <<<g(n), B>>>(W2, as2, ad2, n);
    k_gather2 <<<(n + 31) / 32, B>>>(b2, n, out);
}

// round 14
// speedup vs baseline: 1.2502x; 1.0077x over previous
#include <cuda_runtime.h>
#include <cuda_fp16.h>

#define F_IN  14
#define HEADS 8
#define DIM   8
#define F1    64          // HEADS*DIM
#define NEG   0.2f
#define MAXN  100000
#define MAXE  1600000
#define TILE  1024
#define MAXT  ((MAXN + TILE - 1) / TILE)

// ------------------------- scratch (device globals; no allocs) -------------
__device__ __half g_h1h[MAXN * F1];     // layer1 linear output, fp16 [N,64]
__device__ float g_hL2 [MAXN * F1];     // layer1 final output (ELU'd) = layer2 input
__device__ float g_as1 [MAXN * HEADS];
__device__ float g_ad1 [MAXN * HEADS];
__device__ __half g_h2h[MAXN * DIM];    // layer2 linear output, fp16 [N,8]
__device__ float g_as2 [MAXN];
__device__ float g_ad2 [MAXN];
__device__ int   g_ssrc[MAXE];          // src ids sorted by dst (CSR col idx)
__device__ int   g_rank[MAXE];          // per-edge rank within its dst bucket
__device__ int   g_cnt [MAXN];          // in-degree histogram
__device__ int   g_off [MAXN + 1];      // CSR row offsets
__device__ int   g_bsum[MAXT];          // per-tile sums
__device__ int   g_is64;

// ------------------------- helpers ----------------------------------------
__device__ __forceinline__ float lrelu(float x) { return x > 0.f ? x : NEG * x; }

__device__ __forceinline__ void acc8h(const uint4 u, float w, float4& a0, float4& a1) {
    float2 p0 = __half22float2(*(const __half2*)&u.x);
    float2 p1 = __half22float2(*(const __half2*)&u.y);
    float2 p2 = __half22float2(*(const __half2*)&u.z);
    float2 p3 = __half22float2(*(const __half2*)&u.w);
    a0.x += p0.x * w; a0.y += p0.y * w; a0.z += p1.x * w; a0.w += p1.y * w;
    a1.x += p2.x * w; a1.y += p2.y * w; a1.z += p3.x * w; a1.w += p3.y * w;
}

// ------------------- layer 1 gemm + logits + (cnt zero, dtype detect) ------
// Runs FIRST; independent of CSR build, so it absorbs the init work.
__global__ void __launch_bounds__(256) k_l1(const float* __restrict__ x,
                                            const float* __restrict__ W1,
                                            const float* __restrict__ asrc,
                                            const float* __restrict__ adst,
                                            const unsigned long long* __restrict__ ei64,
                                            int n) {
    __shared__ float sW[F_IN * F1];
    __shared__ float sS[F1], sD[F1];
    int tid = threadIdx.x;
    int gidx = blockIdx.x * 256 + tid;
    if (gidx < n) g_cnt[gidx] = 0;                 // fold: zero histogram
    if (gidx == 0) {                               // fold: dtype detect
        int is64 = 1;
        for (int k = 0; k < 64; k++)
            if (ei64[k] >> 32) { is64 = 0; break; }
        g_is64 = is64;
    }
    for (int i = tid; i < F_IN * F1; i += 256) sW[i] = W1[i];
    if (tid < F1) { sS[tid] = asrc[tid]; sD[tid] = adst[tid]; }
    __syncthreads();

    int node = blockIdx.x * 4 + (tid >> 6);
    int c = tid & 63;
    if (node >= n) return;

    const float* xr = x + node * F_IN;
    float acc = 0.f;
#pragma unroll
    for (int k = 0; k < F_IN; k++) acc += xr[k] * sW[k * F1 + c];
    g_h1h[node * F1 + c] = __float2half_rn(acc);

    float as = acc * sS[c], ad = acc * sD[c];
#pragma unroll
    for (int m = 1; m < 8; m <<= 1) {
        as += __shfl_xor_sync(0xffffffffu, as, m, 8);
        ad += __shfl_xor_sync(0xffffffffu, ad, m, 8);
    }
    if ((c & 7) == 0) {
        int j = node * HEADS + (c >> 3);
        g_as1[j] = as;
        g_ad1[j] = ad;
    }
}

// ------------------------- CSR build ---------------------------------------
// dst histogram + record each edge's rank within its dst bucket
__global__ void k_hist(const void* ei, int e) {
    int i = blockIdx.x * blockDim.x + threadIdx.x;
    if (i >= e) return;
    int d = g_is64 ? (int)((const long long*)ei)[e + i]
                   : ((const int*)ei)[e + i];
    g_rank[i] = atomicAdd(&g_cnt[d], 1);
}

__global__ void __launch_bounds__(256) k_tilesum(int n) {
    __shared__ int sw[8];
    int base = blockIdx.x * TILE;
    int t = threadIdx.x;
    int s = 0;
#pragma unroll
    for (int k = 0; k < 4; k++) {
        int i = base + t * 4 + k;
        if (i < n) s += g_cnt[i];
    }
#pragma unroll
    for (int m = 16; m; m >>= 1) s += __shfl_xor_sync(0xffffffffu, s, m);
    if ((t & 31) == 0) sw[t >> 5] = s;
    __syncthreads();
    if (t == 0) {
        int tot = 0;
#pragma unroll
        for (int w = 0; w < 8; w++) tot += sw[w];
        g_bsum[blockIdx.x] = tot;
    }
}

// per-tile offsets; tile prefix computed by summing preceding g_bsum directly
__global__ void __launch_bounds__(256) k_offsets(int n, int e) {
    __shared__ int sp[256];
    __shared__ int spre;
    int base = blockIdx.x * TILE;
    int t = threadIdx.x;
    if (t == 0) spre = 0;
    __syncthreads();
    // tile prefix: sum of bsum[0..blockIdx)
    int part = 0;
    for (int j = t; j < blockIdx.x; j += 256) part += g_bsum[j];
    if (part) atomicAdd(&spre, part);

    int v[4]; int s = 0;
#pragma unroll
    for (int k = 0; k < 4; k++) {
        int i = base + t * 4 + k;
        v[k] = (i < n) ? g_cnt[i] : 0;
        s += v[k];
    }
    sp[t] = s;
    __syncthreads();
#pragma unroll
    for (int off = 1; off < 256; off <<= 1) {
        int u = (t >= off) ? sp[t - off] : 0;
        __syncthreads();
        sp[t] += u;
        __syncthreads();
    }
    int run = spre + sp[t] - s;
#pragma unroll
    for (int k = 0; k < 4; k++) {
        int i = base + t * 4 + k;
        if (i < n) { g_off[i] = run; run += v[k]; }
    }
    if (blockIdx.x == gridDim.x - 1 && t == 255) g_off[n] = e;
}

// scatter with precomputed ranks: pos = off[d] + rank[i], no atomics
__global__ void k_scatter(const void* ei, int e) {
    int i = blockIdx.x * blockDim.x + threadIdx.x;
    if (i >= e) return;
    int s, d;
    if (g_is64) {
        const long long* p = (const long long*)ei;
        s = (int)p[i]; d = (int)p[e + i];
    } else {
        const int* p = (const int*)ei;
        s = p[i]; d = p[e + i];
    }
    g_ssrc[g_off[d] + g_rank[i]] = s;
}

// ------------------------- layer 1: dst-centric gather + normalize+ELU -----
// 8 threads per node; fp16 feature rows (one uint4 per edge); 2-edge pipeline.
__global__ void __launch_bounds__(256) k_gather1(const float* __restrict__ b1, int n) {
    int tid = threadIdx.x;
    int node = blockIdx.x * 32 + (tid >> 3);
    int h = tid & 7;
    if (node >= n) return;

    int beg = g_off[node], end = g_off[node + 1];
    float ad = g_ad1[node * 8 + h];

    float4 acc0 = make_float4(0.f, 0.f, 0.f, 0.f);
    float4 acc1 = make_float4(0.f, 0.f, 0.f, 0.f);

    float wl = __expf(lrelu(g_as1[node * 8 + h] + ad));
    acc8h(*(const uint4*)(g_h1h + node * F1 + h * 8), wl, acc0, acc1);
    float ws = wl;

    int j = beg;
    for (; j + 1 < end; j += 2) {
        int s0 = g_ssrc[j], s1 = g_ssrc[j + 1];
        float e0 = g_as1[s0 * 8 + h], e1 = g_as1[s1 * 8 + h];
        uint4 u = *(const uint4*)(g_h1h + s0 * F1 + h * 8);
        uint4 v = *(const uint4*)(g_h1h + s1 * F1 + h * 8);
        float w0 = __expf(lrelu(e0 + ad));
        float w1 = __expf(lrelu(e1 + ad));
        acc8h(u, w0, acc0, acc1);
        acc8h(v, w1, acc0, acc1);
        ws += w0 + w1;
    }
    if (j < end) {
        int s = g_ssrc[j];
        float w = __expf(lrelu(g_as1[s * 8 + h] + ad));
        acc8h(*(const uint4*)(g_h1h + s * F1 + h * 8), w, acc0, acc1);
        ws += w;
    }

    float r = __fdividef(1.f, ws);
    float4 bb0 = *(const float4*)(b1 + h * 8);
    float4 bb1 = *(const float4*)(b1 + h * 8 + 4);
    float4 o0, o1;
    o0.x = acc0.x * r + bb0.x; o0.x = o0.x > 0.f ? o0.x : expm1f(o0.x);
    o0.y = acc0.y * r + bb0.y; o0.y = o0.y > 0.f ? o0.y : expm1f(o0.y);
    o0.z = acc0.z * r + bb0.z; o0.z = o0.z > 0.f ? o0.z : expm1f(o0.z);
    o0.w = acc0.w * r + bb0.w; o0.w = o0.w > 0.f ? o0.w : expm1f(o0.w);
    o1.x = acc1.x * r + bb1.x; o1.x = o1.x > 0.f ? o1.x : expm1f(o1.x);
    o1.y = acc1.y * r + bb1.y; o1.y = o1.y > 0.f ? o1.y : expm1f(o1.y);
    o1.z = acc1.z * r + bb1.z; o1.z = o1.z > 0.f ? o1.z : expm1f(o1.z);
    o1.w = acc1.w * r + bb1.w; o1.w = o1.w > 0.f ? o1.w : expm1f(o1.w);
    *(float4*)(g_hL2 + node * F1 + h * 8)     = o0;
    *(float4*)(g_hL2 + node * F1 + h * 8 + 4) = o1;
}

// ------------------------- layer 2: gemm + logits ---------------------------
__global__ void __launch_bounds__(256) k_l2(const float* __restrict__ W2,
                                            const float* __restrict__ asrc,
                                            const float* __restrict__ adst, int n) {
    __shared__ float sW[F1 * DIM], sS[DIM], sD[DIM];
    int tid = threadIdx.x;
    for (int i = tid; i < F1 * DIM; i += 256) sW[i] = W2[i];
    if (tid < DIM) { sS[tid] = asrc[tid]; sD[tid] = adst[tid]; }
    __syncthreads();

    int nidx = blockIdx.x * blockDim.x + tid;
    if (nidx >= n) return;

    float acc[DIM] = {0.f,0.f,0.f,0.f,0.f,0.f,0.f,0.f};
    const float* row = g_hL2 + nidx * F1;
#pragma unroll
    for (int k = 0; k < F1; k += 4) {
        float4 t = *(const float4*)(row + k);
#pragma unroll
        for (int c = 0; c < DIM; c++)
            acc[c] += t.x * sW[k * 8 + c] + t.y * sW[(k + 1) * 8 + c]
                    + t.z * sW[(k + 2) * 8 + c] + t.w * sW[(k + 3) * 8 + c];
    }
    float as = 0.f, ad = 0.f;
#pragma unroll
    for (int c = 0; c < DIM; c++) {
        as += acc[c] * sS[c];
        ad += acc[c] * sD[c];
        g_h2h[nidx * DIM + c] = __float2half_rn(acc[c]);
    }
    g_as2[nidx] = as;
    g_ad2[nidx] = ad;
}

// ------------------------- layer 2: dst-centric gather + finalize ----------
// 8 threads per node; h2 features fp16 (2B loads), as2 fp32.
__global__ void __launch_bounds__(256) k_gather2(const float* __restrict__ b2,
                                                 int n, float* __restrict__ out) {
    int tid = threadIdx.x;
    int node = blockIdx.x * 32 + (tid >> 3);
    int c = tid & 7;
    if (node >= n) return;

    int beg = g_off[node], end = g_off[node + 1];
    float ad = g_ad2[node];

    float wl = __expf(lrelu(g_as2[node] + ad));
    float acc = __half2float(g_h2h[node * DIM + c]) * wl;
    float ws = wl;

    int j = beg;
    for (; j + 3 < end; j += 4) {
        int s0 = g_ssrc[j],     s1 = g_ssrc[j + 1];
        int s2 = g_ssrc[j + 2], s3 = g_ssrc[j + 3];
        float e0 = g_as2[s0], e1 = g_as2[s1], e2 = g_as2[s2], e3 = g_as2[s3];
        float f0 = __half2float(g_h2h[s0 * DIM + c]);
        float f1 = __half2float(g_h2h[s1 * DIM + c]);
        float f2 = __half2float(g_h2h[s2 * DIM + c]);
        float f3 = __half2float(g_h2h[s3 * DIM + c]);
        float w0 = __expf(lrelu(e0 + ad)), w1 = __expf(lrelu(e1 + ad));
        float w2 = __expf(lrelu(e2 + ad)), w3 = __expf(lrelu(e3 + ad));
        acc += w0 * f0 + w1 * f1 + w2 * f2 + w3 * f3;
        ws  += w0 + w1 + w2 + w3;
    }
    for (; j < end; j++) {
        int s = g_ssrc[j];
        float w = __expf(lrelu(g_as2[s] + ad));
        acc += w * __half2float(g_h2h[s * DIM + c]);
        ws += w;
    }
    out[node * DIM + c] = acc * __fdividef(1.f, ws) + __ldg(&b2[c]);
}

// ------------------------- launch -----------------------------------------
extern "C" void kernel_launch(void* const* d_in, const int* in_sizes, int n_in,
                              void* d_out, int out_size) {
    const float* x   = (const float*)d_in[0];
    const void*  ei  = d_in[1];
    const float* W1  = (const float*)d_in[2];
    const float* as1 = (const float*)d_in[3];
    const float* ad1 = (const float*)d_in[4];
    const float* b1  = (const float*)d_in[5];
    const float* W2  = (const float*)d_in[6];
    const float* as2 = (const float*)d_in[7];
    const float* ad2 = (const float*)d_in[8];
    const float* b2  = (const float*)d_in[9];
    float* out = (float*)d_out;

    int n = in_sizes[0] / F_IN;
    int e = in_sizes[1] / 2;
    const int B = 256;
    auto g = [&](long long t) { return (unsigned)((t + B - 1) / B); };
    int ntiles = (n + TILE - 1) / TILE;

    // l1 first (also zeroes histogram + dtype detect), then CSR build
    k_l1      <<<(n + 3) / 4, B>>>(x, W1, as1, ad1, (const unsigned long long*)ei, n);
    k_hist    <<<g(e), B>>>(ei, e);
    k_tilesum <<<ntiles, B>>>(n);
    k_offsets <<<ntiles, B>>>(n, e);
    k_scatter <<<g(e), B>>>(ei, e);

    // layer 1 gather
    k_gather1 <<<(n + 31) / 32, B>>>(b1, n);

    // layer 2
    k_l2      <<<g(n), B>>>(W2, as2, ad2, n);
    k_gather2 <<<(n + 31) / 32, B>>>(b2, n, out);
}

// round 15
// speedup vs baseline: 1.2675x; 1.0139x over previous
#include <cuda_runtime.h>
#include <cuda_fp16.h>

#define F_IN  14
#define HEADS 8
#define DIM   8
#define F1    64          // HEADS*DIM
#define NEG   0.2f
#define MAXN  100000
#define MAXE  1600000
#define TILE  1024
#define MAXT  ((MAXN + TILE - 1) / TILE)

// ------------------------- scratch (device globals; no allocs) -------------
// g_cnt is zero at module load and re-zeroed by k_scatter each launch.
__device__ __half g_h1h[MAXN * F1];     // layer1 linear output, fp16 [N,64]
__device__ float g_hL2 [MAXN * F1];     // layer1 final output (ELU'd) = layer2 input
__device__ float g_as1 [MAXN * HEADS];
__device__ float g_ad1 [MAXN * HEADS];
__device__ __half g_h2h[MAXN * DIM];    // layer2 linear output, fp16 [N,8]
__device__ float g_as2 [MAXN];
__device__ float g_ad2 [MAXN];
__device__ int   g_ssrc[MAXE];          // src ids sorted by dst (CSR col idx)
__device__ int   g_rank[MAXE];          // per-edge rank within its dst bucket
__device__ int   g_cnt [MAXN];          // in-degree histogram (zero-invariant)
__device__ int   g_off [MAXN + 1];      // CSR row offsets
__device__ int   g_bsum[MAXT];          // per-tile sums

// ------------------------- helpers ----------------------------------------
__device__ __forceinline__ float lrelu(float x) { return x > 0.f ? x : NEG * x; }

__device__ __forceinline__ void acc8h(const uint4 u, float w, float4& a0, float4& a1) {
    float2 p0 = __half22float2(*(const __half2*)&u.x);
    float2 p1 = __half22float2(*(const __half2*)&u.y);
    float2 p2 = __half22float2(*(const __half2*)&u.z);
    float2 p3 = __half22float2(*(const __half2*)&u.w);
    a0.x += p0.x * w; a0.y += p0.y * w; a0.z += p1.x * w; a0.w += p1.y * w;
    a1.x += p2.x * w; a1.y += p2.y * w; a1.z += p3.x * w; a1.w += p3.y * w;
}

// per-block edge-dtype detect: warp 0 ballots high bits of first 64 qwords.
// (int64 indices < 1e5 have zero high words; int32 data aliases to nonzero.)
__device__ __forceinline__ int detect_is64(const void* ei, int* sflag) {
    if (threadIdx.x < 32) {
        const unsigned long long* p = (const unsigned long long*)ei;
        unsigned long long v = p[threadIdx.x] | p[threadIdx.x + 32];
        unsigned m = __ballot_sync(0xffffffffu, (v >> 32) != 0ull);
        if (threadIdx.x == 0) *sflag = (m == 0u);
    }
    __syncthreads();
    return *sflag;
}

// -------- fused front end: blocks [0,nbL1) = layer1 gemm+logits;
//          blocks [nbL1, ...) = edge histogram (+rank). Independent work.
__global__ void __launch_bounds__(256) k_l1hist(const float* __restrict__ x,
                                                const float* __restrict__ W1,
                                                const float* __restrict__ asrc,
                                                const float* __restrict__ adst,
                                                const void* ei,
                                                int n, int e, int nbL1) {
    __shared__ float sW[F_IN * F1];
    __shared__ float sS[F1], sD[F1];
    __shared__ int sIs64;
    int tid = threadIdx.x;

    if (blockIdx.x >= nbL1) {
        // ---- histogram part ----
        int is64 = detect_is64(ei, &sIs64);
        int i = (blockIdx.x - nbL1) * 256 + tid;
        if (i < e) {
            int d = is64 ? (int)((const long long*)ei)[e + i]
                         : ((const int*)ei)[e + i];
            g_rank[i] = atomicAdd(&g_cnt[d], 1);
        }
        return;
    }

    // ---- layer1 gemm + logits part ----
    for (int i = tid; i < F_IN * F1; i += 256) sW[i] = W1[i];
    if (tid < F1) { sS[tid] = asrc[tid]; sD[tid] = adst[tid]; }
    __syncthreads();

    int node = blockIdx.x * 4 + (tid >> 6);
    int c = tid & 63;
    if (node >= n) return;

    const float* xr = x + node * F_IN;
    float acc = 0.f;
#pragma unroll
    for (int k = 0; k < F_IN; k++) acc += xr[k] * sW[k * F1 + c];
    g_h1h[node * F1 + c] = __float2half_rn(acc);

    float as = acc * sS[c], ad = acc * sD[c];
#pragma unroll
    for (int m = 1; m < 8; m <<= 1) {
        as += __shfl_xor_sync(0xffffffffu, as, m, 8);
        ad += __shfl_xor_sync(0xffffffffu, ad, m, 8);
    }
    if ((c & 7) == 0) {
        int j = node * HEADS + (c >> 3);
        g_as1[j] = as;
        g_ad1[j] = ad;
    }
}

// ---- hierarchical scan ----------------------------------------------------
__global__ void __launch_bounds__(256) k_tilesum(int n) {
    __shared__ int sw[8];
    int base = blockIdx.x * TILE;
    int t = threadIdx.x;
    int s = 0;
#pragma unroll
    for (int k = 0; k < 4; k++) {
        int i = base + t * 4 + k;
        if (i < n) s += g_cnt[i];
    }
#pragma unroll
    for (int m = 16; m; m >>= 1) s += __shfl_xor_sync(0xffffffffu, s, m);
    if ((t & 31) == 0) sw[t >> 5] = s;
    __syncthreads();
    if (t == 0) {
        int tot = 0;
#pragma unroll
        for (int w = 0; w < 8; w++) tot += sw[w];
        g_bsum[blockIdx.x] = tot;
    }
}

// per-tile offsets; tile prefix computed by summing preceding g_bsum directly
__global__ void __launch_bounds__(256) k_offsets(int n, int e) {
    __shared__ int sp[256];
    __shared__ int spre;
    int base = blockIdx.x * TILE;
    int t = threadIdx.x;
    if (t == 0) spre = 0;
    __syncthreads();
    int part = 0;
    for (int j = t; j < blockIdx.x; j += 256) part += g_bsum[j];
    if (part) atomicAdd(&spre, part);

    int v[4]; int s = 0;
#pragma unroll
    for (int k = 0; k < 4; k++) {
        int i = base + t * 4 + k;
        v[k] = (i < n) ? g_cnt[i] : 0;
        s += v[k];
    }
    sp[t] = s;
    __syncthreads();
#pragma unroll
    for (int off = 1; off < 256; off <<= 1) {
        int u = (t >= off) ? sp[t - off] : 0;
        __syncthreads();
        sp[t] += u;
        __syncthreads();
    }
    int run = spre + sp[t] - s;
#pragma unroll
    for (int k = 0; k < 4; k++) {
        int i = base + t * 4 + k;
        if (i < n) { g_off[i] = run; run += v[k]; }
    }
    if (blockIdx.x == gridDim.x - 1 && t == 255) g_off[n] = e;
}

// scatter with precomputed ranks (no atomics) + re-zero g_cnt for next launch
__global__ void k_scatter(const void* ei, int n, int e) {
    __shared__ int sIs64;
    int is64 = detect_is64(ei, &sIs64);
    int i = blockIdx.x * blockDim.x + threadIdx.x;
    if (i < n) g_cnt[i] = 0;               // restore zero-invariant
    if (i >= e) return;
    int s, d;
    if (is64) {
        const long long* p = (const long long*)ei;
        s = (int)p[i]; d = (int)p[e + i];
    } else {
        const int* p = (const int*)ei;
        s = p[i]; d = p[e + i];
    }
    g_ssrc[g_off[d] + g_rank[i]] = s;
}

// ------------------------- layer 1: dst-centric gather + normalize+ELU -----
__global__ void __launch_bounds__(256) k_gather1(const float* __restrict__ b1, int n) {
    int tid = threadIdx.x;
    int node = blockIdx.x * 32 + (tid >> 3);
    int h = tid & 7;
    if (node >= n) return;

    int beg = g_off[node], end = g_off[node + 1];
    float ad = g_ad1[node * 8 + h];

    float4 acc0 = make_float4(0.f, 0.f, 0.f, 0.f);
    float4 acc1 = make_float4(0.f, 0.f, 0.f, 0.f);

    float wl = __expf(lrelu(g_as1[node * 8 + h] + ad));
    acc8h(*(const uint4*)(g_h1h + node * F1 + h * 8), wl, acc0, acc1);
    float ws = wl;

    int j = beg;
    for (; j + 1 < end; j += 2) {
        int s0 = g_ssrc[j], s1 = g_ssrc[j + 1];
        float e0 = g_as1[s0 * 8 + h], e1 = g_as1[s1 * 8 + h];
        uint4 u = *(const uint4*)(g_h1h + s0 * F1 + h * 8);
        uint4 v = *(const uint4*)(g_h1h + s1 * F1 + h * 8);
        float w0 = __expf(lrelu(e0 + ad));
        float w1 = __expf(lrelu(e1 + ad));
        acc8h(u, w0, acc0, acc1);
        acc8h(v, w1, acc0, acc1);
        ws += w0 + w1;
    }
    if (j < end) {
        int s = g_ssrc[j];
        float w = __expf(lrelu(g_as1[s * 8 + h] + ad));
        acc8h(*(const uint4*)(g_h1h + s * F1 + h * 8), w, acc0, acc1);
        ws += w;
    }

    float r = __fdividef(1.f, ws);
    float4 bb0 = *(const float4*)(b1 + h * 8);
    float4 bb1 = *(const float4*)(b1 + h * 8 + 4);
    float4 o0, o1;
    o0.x = acc0.x * r + bb0.x; o0.x = o0.x > 0.f ? o0.x : expm1f(o0.x);
    o0.y = acc0.y * r + bb0.y; o0.y = o0.y > 0.f ? o0.y : expm1f(o0.y);
    o0.z = acc0.z * r + bb0.z; o0.z = o0.z > 0.f ? o0.z : expm1f(o0.z);
    o0.w = acc0.w * r + bb0.w; o0.w = o0.w > 0.f ? o0.w : expm1f(o0.w);
    o1.x = acc1.x * r + bb1.x; o1.x = o1.x > 0.f ? o1.x : expm1f(o1.x);
    o1.y = acc1.y * r + bb1.y; o1.y = o1.y > 0.f ? o1.y : expm1f(o1.y);
    o1.z = acc1.z * r + bb1.z; o1.z = o1.z > 0.f ? o1.z : expm1f(o1.z);
    o1.w = acc1.w * r + bb1.w; o1.w = o1.w > 0.f ? o1.w : expm1f(o1.w);
    *(float4*)(g_hL2 + node * F1 + h * 8)     = o0;
    *(float4*)(g_hL2 + node * F1 + h * 8 + 4) = o1;
}

// ------------------------- layer 2: gemm + logits ---------------------------
__global__ void __launch_bounds__(256) k_l2(const float* __restrict__ W2,
                                            const float* __restrict__ asrc,
                                            const float* __restrict__ adst, int n) {
    __shared__ float sW[F1 * DIM], sS[DIM], sD[DIM];
    int tid = threadIdx.x;
    for (int i = tid; i < F1 * DIM; i += 256) sW[i] = W2[i];
    if (tid < DIM) { sS[tid] = asrc[tid]; sD[tid] = adst[tid]; }
    __syncthreads();

    int nidx = blockIdx.x * blockDim.x + tid;
    if (nidx >= n) return;

    float acc[DIM] = {0.f,0.f,0.f,0.f,0.f,0.f,0.f,0.f};
    const float* row = g_hL2 + nidx * F1;
#pragma unroll
    for (int k = 0; k < F1; k += 4) {
        float4 t = *(const float4*)(row + k);
#pragma unroll
        for (int c = 0; c < DIM; c++)
            acc[c] += t.x * sW[k * 8 + c] + t.y * sW[(k + 1) * 8 + c]
                    + t.z * sW[(k + 2) * 8 + c] + t.w * sW[(k + 3) * 8 + c];
    }
    float as = 0.f, ad = 0.f;
#pragma unroll
    for (int c = 0; c < DIM; c++) {
        as += acc[c] * sS[c];
        ad += acc[c] * sD[c];
        g_h2h[nidx * DIM + c] = __float2half_rn(acc[c]);
    }
    g_as2[nidx] = as;
    g_ad2[nidx] = ad;
}

// ------------------------- layer 2: dst-centric gather + finalize ----------
__global__ void __launch_bounds__(256) k_gather2(const float* __restrict__ b2,
                                                 int n, float* __restrict__ out) {
    int tid = threadIdx.x;
    int node = blockIdx.x * 32 + (tid >> 3);
    int c = tid & 7;
    if (node >= n) return;

    int beg = g_off[node], end = g_off[node + 1];
    float ad = g_ad2[node];

    float wl = __expf(lrelu(g_as2[node] + ad));
    float acc = __half2float(g_h2h[node * DIM + c]) * wl;
    float ws = wl;

    int j = beg;
    for (; j + 3 < end; j += 4) {
        int s0 = g_ssrc[j],     s1 = g_ssrc[j + 1];
        int s2 = g_ssrc[j + 2], s3 = g_ssrc[j + 3];
        float e0 = g_as2[s0], e1 = g_as2[s1], e2 = g_as2[s2], e3 = g_as2[s3];
        float f0 = __half2float(g_h2h[s0 * DIM + c]);
        float f1 = __half2float(g_h2h[s1 * DIM + c]);
        float f2 = __half2float(g_h2h[s2 * DIM + c]);
        float f3 = __half2float(g_h2h[s3 * DIM + c]);
        float w0 = __expf(lrelu(e0 + ad)), w1 = __expf(lrelu(e1 + ad));
        float w2 = __expf(lrelu(e2 + ad)), w3 = __expf(lrelu(e3 + ad));
        acc += w0 * f0 + w1 * f1 + w2 * f2 + w3 * f3;
        ws  += w0 + w1 + w2 + w3;
    }
    for (; j < end; j++) {
        int s = g_ssrc[j];
        float w = __expf(lrelu(g_as2[s] + ad));
        acc += w * __half2float(g_h2h[s * DIM + c]);
        ws += w;
    }
    out[node * DIM + c] = acc * __fdividef(1.f, ws) + __ldg(&b2[c]);
}

// ------------------------- launch -----------------------------------------
extern "C" void kernel_launch(void* const* d_in, const int* in_sizes, int n_in,
                              void* d_out, int out_size) {
    const float* x   = (const float*)d_in[0];
    const void*  ei  = d_in[1];
    const float* W1  = (const float*)d_in[2];
    const float* as1 = (const float*)d_in[3];
    const float* ad1 = (const float*)d_in[4];
    const float* b1  = (const float*)d_in[5];
    const float* W2  = (const float*)d_in[6];
    const float* as2 = (const float*)d_in[7];
    const float* ad2 = (const float*)d_in[8];
    const float* b2  = (const float*)d_in[9];
    float* out = (float*)d_out;

    int n = in_sizes[0] / F_IN;
    int e = in_sizes[1] / 2;
    const int B = 256;
    auto g = [&](long long t) { return (unsigned)((t + B - 1) / B); };
    int ntiles = (n + TILE - 1) / TILE;
    int nbL1   = (n + 3) / 4;
    int nbHist = g(e);
    int nbScat = g(e > n ? e : n);          // scatter grid must also cover cnt zeroing

    // fused front end (l1 || hist), then scan -> scatter
    k_l1hist  <<<nbL1 + nbHist, B>>>(x, W1, as1, ad1, ei, n, e, nbL1);
    k_tilesum <<<ntiles, B>>>(n);
    k_offsets <<<ntiles, B>>>(n, e);
    k_scatter <<<nbScat, B>>>(ei, n, e);

    // layer 1 gather
    k_gather1 <<<(n + 31) / 32, B>>>(b1, n);

    // layer 2
    k_l2      <<<g(n), B>>>(W2, as2, ad2, n);
    k_gather2 <<<(n + 31) / 32, B>>>(b2, n, out);
}